// round 12
// baseline (speedup 1.0000x reference)
#include <cuda_runtime.h>

// DegreePrediction: y[u] = sum_{s,t,v} (x*W_t)[s,t] * (W_r*r_zeros + r_const)[s,t,u,v]
// N = 80. Three 80^4 fp32 tensors (491.5 MB) streamed once.
//
// R12: drain-tapered block sizes. R7's DRAM=81% decomposes as ~99% mid-kernel
// + a ~14us unbackfilled drain tail (last resident generation of 28.7us
// blocks). Blocks are scheduled ~in bid order, so give late bids less work:
//   bids [0,1200):    4 slices   (4800)
//   bids [1200,1600): 2 slices   ( 800)
//   bids [1600,2400): 1 slice    ( 800)
// Tail now drains with 7us blocks (~3.5us loss). Mainloop = R7's 48-reg
// register-prefetch pipeline over a contiguous slice run (pointer increments),
// epilogue = R7's STS transpose + gather + acq_rel-counter finalize.
//
// Layout: slice = 1600 contiguous float4 = 5*320; run starts slice-aligned, so
// iter j of each slice reads float4 tid+320*j -> u = tid/20 + 16*j.

#define NN 80
#define SLICE_F4 1600
#define THREADS 320
#define J_ITERS 5
#define GRID_TOTAL 2400

__device__ float    g_scratch[NN];   // zero at load; kernel restores to zero
__device__ unsigned g_count;         // ditto

__device__ __forceinline__ unsigned atom_inc_acq_rel(unsigned* p) {
    unsigned old;
    asm volatile("atom.add.acq_rel.gpu.global.u32 %0, [%1], 1;"
                 : "=r"(old) : "l"(p) : "memory");
    return old;
}

__global__ __launch_bounds__(THREADS, 4)
void degree_pred_kernel(const float* __restrict__ x,
                        const float* __restrict__ r_zeros,
                        const float* __restrict__ r_const,
                        const float* __restrict__ weights_t,
                        const float* __restrict__ weights_r,
                        float* __restrict__ out)
{
    __shared__ float y_part[J_ITERS][THREADS];
    __shared__ bool is_last;
    const int tid = threadIdx.x;
    const int bid = blockIdx.x;

    // drain taper: late bids get less work; runs are contiguous
    int ns, s0;
    if (bid < 1200)      { ns = 4; s0 = bid * 4; }
    else if (bid < 1600) { ns = 2; s0 = 4800 + (bid - 1200) * 2; }
    else                 { ns = 1; s0 = 5600 + (bid - 1600); }

    const size_t fbase = (size_t)s0 * SLICE_F4 + tid;
    const float4* pz = reinterpret_cast<const float4*>(r_zeros)   + fbase;
    const float4* pc = reinterpret_cast<const float4*>(r_const)   + fbase;
    const float4* pw = reinterpret_cast<const float4*>(weights_r) + fbase;

    float acc[J_ITERS];
#pragma unroll
    for (int j = 0; j < J_ITERS; j++) acc[j] = 0.0f;

    // prologue: prefetch iteration 0 and the first slice scalar
    float a_cur = __ldg(&x[s0]) * __ldg(&weights_t[s0]);
    float4 z0 = __ldcs(pz);
    float4 c0 = __ldcs(pc);
    float4 w0 = __ldcs(pw);

    for (int ss = 0; ss < ns; ss++) {
        const bool last_slice = (ss == ns - 1);
        const int sn = last_slice ? (s0 + ss) : (s0 + ss + 1);   // clamped
        const float a_next = __ldg(&x[sn]) * __ldg(&weights_t[sn]);

#pragma unroll
        for (int j = 0; j < J_ITERS; j++) {
            pz += THREADS; pc += THREADS; pw += THREADS;   // next iter's data

            float4 z1, c1, w1;
            if (j < J_ITERS - 1 || !last_slice) {          // j<4: always true
                z1 = __ldcs(pz);
                c1 = __ldcs(pc);
                w1 = __ldcs(pw);
            }

            float t = (c0.x + c0.y) + (c0.z + c0.w);
            t = fmaf(w0.x, z0.x, t);
            t = fmaf(w0.y, z0.y, t);
            t = fmaf(w0.z, z0.z, t);
            t = fmaf(w0.w, z0.w, t);
            acc[j] = fmaf(a_cur, t, acc[j]);

            z0 = z1; c0 = c1; w0 = w1;
        }
        a_cur = a_next;
    }

    // ---- epilogue (once per block): STS transpose + 80-thread gather ----
#pragma unroll
    for (int j = 0; j < J_ITERS; j++)
        y_part[j][tid] = acc[j];
    __syncthreads();

    if (tid < NN) {
        const int u = tid;
        const int j = u >> 4;            // u / 16
        const int b = (u & 15) * 20;     // first of 20 contributing threads
        float s = 0.0f;
#pragma unroll
        for (int d = 0; d < 20; d++)
            s += y_part[j][b + d];
        atomicAdd(&g_scratch[u], s);     // relaxed; published by acq_rel below
    }
    __syncthreads();

    // ---- last-block finalize ----
    if (tid == 0)
        is_last = (atom_inc_acq_rel(&g_count) == (unsigned)(GRID_TOTAL - 1));
    __syncthreads();

    if (is_last) {
        if (tid < NN) {
            float v = __ldcg(&g_scratch[tid]);   // L2 read, coherent w/ atomics
            out[tid] = v;
            g_scratch[tid] = 0.0f;               // restore initial state
        }
        __syncthreads();
        if (tid == 0) g_count = 0u;              // restore initial state
    }
}

extern "C" void kernel_launch(void* const* d_in, const int* in_sizes, int n_in,
                              void* d_out, int out_size)
{
    const float* x         = (const float*)d_in[0];
    const float* r_zeros   = (const float*)d_in[1];
    const float* r_const   = (const float*)d_in[2];
    const float* weights_t = (const float*)d_in[3];
    const float* weights_r = (const float*)d_in[4];
    float* out = (float*)d_out;

    degree_pred_kernel<<<GRID_TOTAL, THREADS>>>(x, r_zeros, r_const,
                                                weights_t, weights_r, out);
}

// round 13
// speedup vs baseline: 1.0203x; 1.0203x over previous
#include <cuda_runtime.h>

// DegreePrediction: y[u] = sum_{s,t,v} (x*W_t)[s,t] * (W_r*r_zeros + r_const)[s,t,u,v]
// N = 80. Three 80^4 fp32 tensors (491.5 MB) streamed once.
//
// R13: drain taper with R7's EXACT mainloop. R12 accidentally tested the taper
// on a pointer-increment loop (serial IADD chains -> no LDG front-batching,
// alu 4.7%, DRAM 78.9%). Here the slice count is a template parameter, so all
// three taper phases get the fully-unrolled immediate-offset prefetch pipeline
// (60 LDG.128 [base+imm] for K=4) that made R7 the fastest kernel (81% DRAM):
//   bids [0,1200):    K=4  (4800 slices)  == R7 body
//   bids [1200,1600): K=2  ( 800 slices)
//   bids [1600,2400): K=1  ( 800 slices)  ~7us drain blocks
//
// Layout: slice = 1600 contiguous float4 = 5*320; iter j reads float4
// tid + 320*j of its slice -> u = tid/20 + 16*j (constant per thread,j).

#define NN 80
#define SLICE_F4 1600
#define THREADS 320
#define J_ITERS 5
#define B4 1200
#define B2 400
#define B1 800
#define GRID_TOTAL (B4 + B2 + B1)   // 2400

__device__ float    g_scratch[NN];   // zero at load; kernel restores to zero
__device__ unsigned g_count;         // ditto

__device__ __forceinline__ unsigned atom_inc_acq_rel(unsigned* p) {
    unsigned old;
    asm volatile("atom.add.acq_rel.gpu.global.u32 %0, [%1], 1;"
                 : "=r"(old) : "l"(p) : "memory");
    return old;
}

template <int K>
__device__ __forceinline__ void stream_slices(
    const float* __restrict__ x, const float* __restrict__ wt,
    const float4* __restrict__ Z, const float4* __restrict__ C,
    const float4* __restrict__ W,
    int s0, int tid, float acc[J_ITERS])
{
    float a[K];
#pragma unroll
    for (int k = 0; k < K; k++)
        a[k] = __ldg(&x[s0 + k]) * __ldg(&wt[s0 + k]);

    const size_t base = (size_t)s0 * SLICE_F4 + tid;
    const float4* __restrict__ rz = Z + base;
    const float4* __restrict__ rc = C + base;
    const float4* __restrict__ rw = W + base;

    // software pipeline, fully unrolled: all offsets are compile-time
    // immediates -> ptxas front-batches the LDG.128s.
    float4 z0 = __ldcs(rz);
    float4 c0 = __ldcs(rc);
    float4 w0 = __ldcs(rw);

#pragma unroll
    for (int it = 0; it < K * J_ITERS; it++) {
        const int k = it / J_ITERS;
        const int j = it % J_ITERS;

        float4 z1, c1, w1;
        if (it < K * J_ITERS - 1) {
            const int itn = it + 1;
            const int pn = THREADS * (itn % J_ITERS) + SLICE_F4 * (itn / J_ITERS);
            z1 = __ldcs(rz + pn);
            c1 = __ldcs(rc + pn);
            w1 = __ldcs(rw + pn);
        }

        float t = (c0.x + c0.y) + (c0.z + c0.w);
        t = fmaf(w0.x, z0.x, t);
        t = fmaf(w0.y, z0.y, t);
        t = fmaf(w0.z, z0.z, t);
        t = fmaf(w0.w, z0.w, t);
        acc[j] = fmaf(a[k], t, acc[j]);

        z0 = z1; c0 = c1; w0 = w1;
    }
}

__global__ __launch_bounds__(THREADS, 4)
void degree_pred_kernel(const float* __restrict__ x,
                        const float* __restrict__ r_zeros,
                        const float* __restrict__ r_const,
                        const float* __restrict__ weights_t,
                        const float* __restrict__ weights_r,
                        float* __restrict__ out)
{
    __shared__ float y_part[J_ITERS][THREADS];
    __shared__ bool is_last;
    const int tid = threadIdx.x;
    const int bid = blockIdx.x;

    const float4* __restrict__ Z = reinterpret_cast<const float4*>(r_zeros);
    const float4* __restrict__ C = reinterpret_cast<const float4*>(r_const);
    const float4* __restrict__ W = reinterpret_cast<const float4*>(weights_r);

    float acc[J_ITERS];
#pragma unroll
    for (int j = 0; j < J_ITERS; j++) acc[j] = 0.0f;

    if (bid < B4) {
        stream_slices<4>(x, weights_t, Z, C, W, bid * 4, tid, acc);
    } else if (bid < B4 + B2) {
        stream_slices<2>(x, weights_t, Z, C, W, 4 * B4 + (bid - B4) * 2, tid, acc);
    } else {
        stream_slices<1>(x, weights_t, Z, C, W,
                         4 * B4 + 2 * B2 + (bid - B4 - B2), tid, acc);
    }

    // ---- epilogue (once per block): STS transpose + 80-thread gather ----
#pragma unroll
    for (int j = 0; j < J_ITERS; j++)
        y_part[j][tid] = acc[j];
    __syncthreads();

    if (tid < NN) {
        const int u = tid;
        const int j = u >> 4;            // u / 16
        const int b = (u & 15) * 20;     // first of 20 contributing threads
        float s = 0.0f;
#pragma unroll
        for (int d = 0; d < 20; d++)
            s += y_part[j][b + d];
        atomicAdd(&g_scratch[u], s);     // relaxed; published by acq_rel below
    }
    __syncthreads();

    // ---- last-block finalize ----
    if (tid == 0)
        is_last = (atom_inc_acq_rel(&g_count) == (unsigned)(GRID_TOTAL - 1));
    __syncthreads();

    if (is_last) {
        if (tid < NN) {
            float v = __ldcg(&g_scratch[tid]);   // L2 read, coherent w/ atomics
            out[tid] = v;
            g_scratch[tid] = 0.0f;               // restore initial state
        }
        __syncthreads();
        if (tid == 0) g_count = 0u;              // restore initial state
    }
}

extern "C" void kernel_launch(void* const* d_in, const int* in_sizes, int n_in,
                              void* d_out, int out_size)
{
    const float* x         = (const float*)d_in[0];
    const float* r_zeros   = (const float*)d_in[1];
    const float* r_const   = (const float*)d_in[2];
    const float* weights_t = (const float*)d_in[3];
    const float* weights_r = (const float*)d_in[4];
    float* out = (float*)d_out;

    degree_pred_kernel<<<GRID_TOTAL, THREADS>>>(x, r_zeros, r_const,
                                                weights_t, weights_r, out);
}